// round 1
// baseline (speedup 1.0000x reference)
#include <cuda_runtime.h>
#include <cstdint>
#include <cstddef>

#define Bn 16
#define Tn 1024
#define DIN 4608
#define DRED 128
#define Hn 32
#define G3 96
#define TAUc 12

// Scratch (no dynamic allocation allowed)
__device__ float g_Wc[G3 * DIN];          // combined weight w_ih @ w_dr  [96,4608]
__device__ float g_bc[G3];                // combined bias
__device__ float g_gi[Bn * Tn * G3];      // input gates for all timesteps
__device__ float g_hs[Bn * Tn * Hn];      // GRU hidden states

__device__ __forceinline__ unsigned long long fma2(unsigned long long a, unsigned long long b, unsigned long long c) {
    unsigned long long d;
    asm("fma.rn.f32x2 %0, %1, %2, %3;" : "=l"(d) : "l"(a), "l"(b), "l"(c));
    return d;
}
__device__ __forceinline__ unsigned long long add2(unsigned long long a, unsigned long long b) {
    unsigned long long d;
    asm("add.rn.f32x2 %0, %1, %2;" : "=l"(d) : "l"(a), "l"(b));
    return d;
}
__device__ __forceinline__ unsigned long long pack2(float x) {
    unsigned long long d;
    asm("mov.b64 %0, {%1, %1};" : "=l"(d) : "f"(x));
    return d;
}
__device__ __forceinline__ float sigm(float x) { return __fdividef(1.f, 1.f + __expf(-x)); }
__device__ __forceinline__ float tanhfast(float x) { return __fdividef(2.f, 1.f + __expf(-2.f * x)) - 1.f; }

// ---------------------------------------------------------------------------
// Kernel A: W_comb[g][d] = sum_r w_ih[g][r] * w_dr[r][d]
// grid (36, 2), block 128. Each block: 128 d-columns x 48 g-rows.
// ---------------------------------------------------------------------------
__global__ void k_wcomb(const float* __restrict__ w_ih, const float* __restrict__ w_dr) {
    __shared__ float swt[DRED][48];   // [r][gg]
    const int gbase = blockIdx.y * 48;
    for (int idx = threadIdx.x; idx < DRED * 48; idx += 128) {
        int r = idx / 48, gg = idx % 48;
        swt[r][gg] = w_ih[(gbase + gg) * DRED + r];
    }
    __syncthreads();
    const int d = blockIdx.x * 128 + threadIdx.x;
    float acc[48];
#pragma unroll
    for (int gg = 0; gg < 48; gg++) acc[gg] = 0.f;
#pragma unroll 4
    for (int r = 0; r < DRED; r++) {
        float a = w_dr[r * DIN + d];
#pragma unroll
        for (int gg = 0; gg < 48; gg++) acc[gg] = fmaf(swt[r][gg], a, acc[gg]);
    }
    for (int gg = 0; gg < 48; gg++) g_Wc[(size_t)(gbase + gg) * DIN + d] = acc[gg];
}

// b_comb[g] = b_ih[g] + sum_r w_ih[g][r] * b_dr[r]
__global__ void k_bcomb(const float* __restrict__ w_ih, const float* __restrict__ b_dr,
                        const float* __restrict__ b_ih) {
    int g = threadIdx.x;
    if (g < G3) {
        float acc = b_ih[g];
        for (int r = 0; r < DRED; r++) acc = fmaf(w_ih[g * DRED + r], b_dr[r], acc);
        g_bc[g] = acc;
    }
}

// ---------------------------------------------------------------------------
// Kernel B: gi[M=16384, N=96] = x[M, 4608] @ W_comb^T + b_comb
// BM=64, BN=96, BK=32; 256 threads; thread tile 4x6, f32x2-packed FMA.
// ---------------------------------------------------------------------------
__global__ __launch_bounds__(256) void k_gemm(const float* __restrict__ x) {
    __shared__ float As[32][68];   // [k][m], padded
    __shared__ float Bs[32][98];   // [k][n], padded

    const int tid = threadIdx.x;
    const int m0 = blockIdx.x * 64;
    const int lrow = tid >> 3, lc4 = tid & 7;
    const int ty = tid >> 4, tx = tid & 15;

    unsigned long long acc[4][3];
#pragma unroll
    for (int i = 0; i < 4; i++)
#pragma unroll
        for (int p = 0; p < 3; p++) acc[i][p] = 0ull;

    for (int k0 = 0; k0 < DIN; k0 += 32) {
#pragma unroll
        for (int p = 0; p < 2; p++) {
            int r = lrow + 32 * p;
            float4 v = *(const float4*)&x[(size_t)(m0 + r) * DIN + k0 + lc4 * 4];
            As[lc4 * 4 + 0][r] = v.x; As[lc4 * 4 + 1][r] = v.y;
            As[lc4 * 4 + 2][r] = v.z; As[lc4 * 4 + 3][r] = v.w;
        }
#pragma unroll
        for (int p = 0; p < 3; p++) {
            int n = lrow + 32 * p;
            float4 v = *(const float4*)&g_Wc[(size_t)n * DIN + k0 + lc4 * 4];
            Bs[lc4 * 4 + 0][n] = v.x; Bs[lc4 * 4 + 1][n] = v.y;
            Bs[lc4 * 4 + 2][n] = v.z; Bs[lc4 * 4 + 3][n] = v.w;
        }
        __syncthreads();
#pragma unroll
        for (int kk = 0; kk < 32; kk++) {
            float4 a = *(const float4*)&As[kk][ty * 4];
            const unsigned long long* bp = (const unsigned long long*)&Bs[kk][tx * 6];
            unsigned long long b0 = bp[0], b1 = bp[1], b2 = bp[2];
            unsigned long long A0 = pack2(a.x), A1 = pack2(a.y), A2 = pack2(a.z), A3 = pack2(a.w);
            acc[0][0] = fma2(A0, b0, acc[0][0]); acc[0][1] = fma2(A0, b1, acc[0][1]); acc[0][2] = fma2(A0, b2, acc[0][2]);
            acc[1][0] = fma2(A1, b0, acc[1][0]); acc[1][1] = fma2(A1, b1, acc[1][1]); acc[1][2] = fma2(A1, b2, acc[1][2]);
            acc[2][0] = fma2(A2, b0, acc[2][0]); acc[2][1] = fma2(A2, b1, acc[2][1]); acc[2][2] = fma2(A2, b2, acc[2][2]);
            acc[3][0] = fma2(A3, b0, acc[3][0]); acc[3][1] = fma2(A3, b1, acc[3][1]); acc[3][2] = fma2(A3, b2, acc[3][2]);
        }
        __syncthreads();
    }

    unsigned long long bias[3];
    {
        const unsigned long long* bb = (const unsigned long long*)&g_bc[tx * 6];
        bias[0] = bb[0]; bias[1] = bb[1]; bias[2] = bb[2];
    }
#pragma unroll
    for (int i = 0; i < 4; i++) {
        size_t row = (size_t)(m0 + ty * 4 + i) * G3 + tx * 6;
        unsigned long long* op = (unsigned long long*)&g_gi[row];
        op[0] = add2(acc[i][0], bias[0]);
        op[1] = add2(acc[i][1], bias[1]);
        op[2] = add2(acc[i][2], bias[2]);
    }
}

// ---------------------------------------------------------------------------
// Kernel C: GRU recurrence. grid 16 (one per batch), block 96 (one per gate row).
// gi precomputed; per step only gh = h @ w_hh^T is h-dependent.
// ---------------------------------------------------------------------------
__global__ __launch_bounds__(96) void k_gru(const float* __restrict__ w_hh,
                                            const float* __restrict__ b_hh) {
    __shared__ __align__(16) float sh[Hn];
    __shared__ float sA[G3];
    __shared__ float sHN[Hn];
    const int b = blockIdx.x, g = threadIdx.x, j = g & 31;

    float whh[Hn];
#pragma unroll
    for (int i = 0; i < 8; i++) {
        float4 v = ((const float4*)(w_hh + g * Hn))[i];
        whh[4 * i] = v.x; whh[4 * i + 1] = v.y; whh[4 * i + 2] = v.z; whh[4 * i + 3] = v.w;
    }
    const float bhh = b_hh[g];
    if (g < Hn) sh[g] = 0.f;
    __syncthreads();

    const float* gip = g_gi + (size_t)b * Tn * G3;
    float* hsp = g_hs + (size_t)b * Tn * Hn;
    float gcur = gip[g];

    for (int t = 0; t < Tn; t++) {
        float gnext = gip[(t + 1 < Tn ? t + 1 : t) * G3 + g];   // prefetch
        float a0 = 0.f, a1 = 0.f, a2 = 0.f, a3 = 0.f;
#pragma unroll
        for (int i = 0; i < 8; i++) {
            float4 h4 = *(const float4*)&sh[4 * i];
            a0 = fmaf(h4.x, whh[4 * i + 0], a0);
            a1 = fmaf(h4.y, whh[4 * i + 1], a1);
            a2 = fmaf(h4.z, whh[4 * i + 2], a2);
            a3 = fmaf(h4.w, whh[4 * i + 3], a3);
        }
        float gh = (a0 + a1) + (a2 + a3) + bhh;
        if (g < 64) sA[g] = gcur + gh;
        else { sA[g] = gcur; sHN[j] = gh; }
        __syncthreads();
        if (g < Hn) {
            float r = sigm(sA[j]);
            float z = sigm(sA[Hn + j]);
            float n = tanhfast(sA[64 + j] + r * sHN[j]);
            float hnew = (1.f - z) * n + z * sh[j];
            hsp[t * Hn + j] = hnew;
            sh[j] = hnew;
        }
        __syncthreads();
        gcur = gnext;
    }
}

// ---------------------------------------------------------------------------
// Kernel D: quality head + pooling + masked mean + output heads.
// grid 16 (one per batch), block 256.
// ---------------------------------------------------------------------------
__global__ __launch_bounds__(256) void k_pool(const int* __restrict__ x_len,
    const float* __restrict__ w_reg, const float* __restrict__ b_reg,
    const float* __restrict__ w_nlm1, const float* __restrict__ b_nlm1,
    const float* __restrict__ w_nlm2, const float* __restrict__ b_nlm2,
    const float* __restrict__ w_lm, const float* __restrict__ b_lm,
    float* __restrict__ out)
{
    __shared__ float sq[Tn];
    __shared__ float red[256];
    __shared__ float swr[Hn];
    const int b = blockIdx.x, tid = threadIdx.x;
    if (tid < Hn) swr[tid] = w_reg[tid];
    __syncthreads();
    const float breg = b_reg[0];

    for (int t = tid; t < Tn; t += 256) {
        const float4* hr = (const float4*)(g_hs + ((size_t)b * Tn + t) * Hn);
        float acc = breg;
#pragma unroll
        for (int i = 0; i < 8; i++) {
            float4 v = hr[i];
            acc += v.x * swr[4 * i] + v.y * swr[4 * i + 1] + v.z * swr[4 * i + 2] + v.w * swr[4 * i + 3];
        }
        sq[t] = acc;
    }
    __syncthreads();

    const int len = x_len[b];
    float local = 0.f;
    for (int t = tid; t < Tn; t += 256) {
        if (t < len) {
            // backward min over [t-11, t] (left pad +inf)
            float mn = sq[t];
#pragma unroll
            for (int k = 1; k < TAUc; k++) {
                int idx = t - k;
                float v = (idx >= 0) ? sq[idx] : 3.402823466e38f;
                mn = fminf(mn, v);
            }
            // exp-weighted forward average over [t, t+11]; OOR/invalid -> QP, exp(-QP)=0
            float num = 0.f, den = 0.f;
#pragma unroll
            for (int k = 0; k < TAUc; k++) {
                int idx = t + k;
                float v = (idx < len) ? sq[idx] : 1e4f;
                float e = __expf(-v);
                num = fmaf(v, e, num);
                den += e;
            }
            float m = num / den;   // the /tau in both means cancels
            local += 0.5f * m + 0.5f * mn;
        }
    }
    red[tid] = local;
    __syncthreads();
    for (int s = 128; s > 0; s >>= 1) {
        if (tid < s) red[tid] += red[tid + s];
        __syncthreads();
    }
    if (tid == 0) {
        float rel = red[0] / (float)len;
        float relative = 1.f / (1.f + expf(-rel));
        float mapped = (1.f / (1.f + expf(-(relative * w_nlm1[0] + b_nlm1[0])))) * w_nlm2[0] + b_nlm2[0];
        float aligned = mapped * w_lm[0] + b_lm[0];
        out[b] = relative;
        out[Bn + b] = mapped;
        out[2 * Bn + b] = aligned;
    }
}

extern "C" void kernel_launch(void* const* d_in, const int* in_sizes, int n_in,
                              void* d_out, int out_size) {
    const float* x      = (const float*)d_in[0];
    const int*   x_len  = (const int*)d_in[1];
    const float* w_dr   = (const float*)d_in[2];
    const float* b_dr   = (const float*)d_in[3];
    const float* w_ih   = (const float*)d_in[4];
    const float* w_hh   = (const float*)d_in[5];
    const float* b_ih   = (const float*)d_in[6];
    const float* b_hh   = (const float*)d_in[7];
    const float* w_reg  = (const float*)d_in[8];
    const float* b_reg  = (const float*)d_in[9];
    const float* w_nlm1 = (const float*)d_in[10];
    const float* b_nlm1 = (const float*)d_in[11];
    const float* w_nlm2 = (const float*)d_in[12];
    const float* b_nlm2 = (const float*)d_in[13];
    const float* w_lm   = (const float*)d_in[14];
    const float* b_lm   = (const float*)d_in[15];
    float* out = (float*)d_out;

    k_wcomb<<<dim3(36, 2), 128>>>(w_ih, w_dr);
    k_bcomb<<<1, 128>>>(w_ih, b_dr, b_ih);
    k_gemm<<<256, 256>>>(x);
    k_gru<<<16, 96>>>(w_hh, b_hh);
    k_pool<<<16, 256>>>(x_len, w_reg, b_reg, w_nlm1, b_nlm1, w_nlm2, b_nlm2, w_lm, b_lm, out);
}